// round 1
// baseline (speedup 1.0000x reference)
#include <cuda_runtime.h>
#include <cuda_bf16.h>

#define NROWS   8192
#define NF      1024
#define NTHREADS 256
#define NBLOCKS 1024
#define SW_PAD  9          // padded stride for conflict-free LDS

__global__ __launch_bounds__(NTHREADS)
void kan_fused_kernel(const float* __restrict__ x,
                      const float* __restrict__ lnw,
                      const float* __restrict__ lnb,
                      const float* __restrict__ sw,
                      const float* __restrict__ bw,
                      const float* __restrict__ grid,
                      float* __restrict__ out)
{
    __shared__ float s_sw[NF * SW_PAD];   // 36 KB padded spline weights
    __shared__ float s_sum[8], s_sum2[8];

    const int tid  = threadIdx.x;
    const int wid  = tid >> 5;
    const int lane = tid & 31;

    // Stage spline weights (8 coeffs per feature, padded to 9)
    for (int f = tid; f < NF; f += NTHREADS) {
        float4 a = *reinterpret_cast<const float4*>(sw + f * 8);
        float4 b = *reinterpret_cast<const float4*>(sw + f * 8 + 4);
        float* d = s_sw + f * SW_PAD;
        d[0] = a.x; d[1] = a.y; d[2] = a.z; d[3] = a.w;
        d[4] = b.x; d[5] = b.y; d[6] = b.z; d[7] = b.w;
    }

    // Grid is uniform & shared across features: derive g0, h from endpoints
    const float g0    = grid[0];
    const float g11   = grid[11];
    const float inv_h = 11.0f / (g11 - g0);

    // Per-thread fixed feature params (features tid + e*256)
    float w_ln[4], b_ln[4], w_bs[4];
    #pragma unroll
    for (int e = 0; e < 4; e++) {
        int f = tid + e * NTHREADS;
        w_ln[e] = lnw[f];
        b_ln[e] = lnb[f];
        w_bs[e] = bw[f];
    }
    __syncthreads();

    for (int row = blockIdx.x; row < NROWS; row += NBLOCKS) {
        const float* xr = x + (size_t)row * NF;

        // Load 4 values (stride-256: perfectly coalesced) + local sums
        float v[4];
        float sum = 0.0f, sum2 = 0.0f;
        #pragma unroll
        for (int e = 0; e < 4; e++) {
            v[e] = xr[tid + e * NTHREADS];
            sum  += v[e];
            sum2 += v[e] * v[e];
        }

        // Warp reduce
        #pragma unroll
        for (int off = 16; off; off >>= 1) {
            sum  += __shfl_xor_sync(0xffffffffu, sum,  off);
            sum2 += __shfl_xor_sync(0xffffffffu, sum2, off);
        }
        if (lane == 0) { s_sum[wid] = sum; s_sum2[wid] = sum2; }
        __syncthreads();

        float tot = 0.0f, tot2 = 0.0f;
        #pragma unroll
        for (int i = 0; i < 8; i++) { tot += s_sum[i]; tot2 += s_sum2[i]; }
        __syncthreads();   // protect s_sum before next row's writes

        const float mu   = tot  * (1.0f / NF);
        const float var  = tot2 * (1.0f / NF) - mu * mu;
        const float rstd = rsqrtf(var + 1e-5f);

        float* outr = out + (size_t)row * NF;

        #pragma unroll
        for (int e = 0; e < 4; e++) {
            const int f = tid + e * NTHREADS;
            const float n = (v[e] - mu) * rstd * w_ln[e] + b_ln[e];

            // ---- analytic uniform cubic B-spline ----
            const float xn = (n - g0) * inv_h;        // in knot units
            const float fj = floorf(xn);
            const int   j  = (int)fj;
            const float t  = xn - fj;
            const float u  = 1.0f - t;
            const float t2 = t * t;
            const float t3 = t2 * t;
            const float B0 = u * u * u * (1.0f / 6.0f);
            const float B1 = (3.0f * t3 - 6.0f * t2 + 4.0f) * (1.0f / 6.0f);
            const float B2 = (-3.0f * t3 + 3.0f * t2 + 3.0f * t + 1.0f) * (1.0f / 6.0f);
            const float B3 = t3 * (1.0f / 6.0f);

            float s = 0.0f;
            if (j >= 0 && j <= 10) {
                const int i0 = j - 3;
                const float* wf = s_sw + f * SW_PAD;
                if (i0 + 0 >= 0)            s = fmaf(B0, wf[i0 + 0], s);
                if (i0 + 1 >= 0 && i0 + 1 < 8) s = fmaf(B1, wf[i0 + 1], s);
                if (i0 + 2 >= 0 && i0 + 2 < 8) s = fmaf(B2, wf[i0 + 2], s);
                if (i0 + 3 < 8)             s = fmaf(B3, wf[i0 + 3], s);
            }

            // silu residual
            const float ex  = __expf(-n);
            const float sil = __fdividef(n, 1.0f + ex);

            outr[f] = s + w_bs[e] * sil;
        }
    }
}

extern "C" void kernel_launch(void* const* d_in, const int* in_sizes, int n_in,
                              void* d_out, int out_size)
{
    const float* x    = (const float*)d_in[0];
    const float* lnw  = (const float*)d_in[1];
    const float* lnb  = (const float*)d_in[2];
    const float* sw   = (const float*)d_in[3];
    const float* bw   = (const float*)d_in[4];
    const float* grid = (const float*)d_in[5];
    float* out = (float*)d_out;

    kan_fused_kernel<<<NBLOCKS, NTHREADS>>>(x, lnw, lnb, sw, bw, grid, out);
}